// round 10
// baseline (speedup 1.0000x reference)
#include <cuda_runtime.h>
#include <cstdint>
#include <math.h>

// Problem constants (fixed by reference)
#define BB 256
#define PP 16
#define LL 4
#define EE 128
#define NPAIR 4096          // B*P
#define NNODE 512
#define C1 512
#define C2 256
#define LIST_CAP 64
#define XSTR 132            // padded stride (floats) for ws and xs
#define ITEMS_MAX 768       // >= sum ceil(k/16) (proven bound 768)
#define PGRID 296           // persistent blocks (2 per SM x 148)

typedef unsigned long long ull;

// ---------------- device scratch (no allocations allowed) ----------------
__device__ float g_bufA[NPAIR * 2 * EE];   // 4 MB ping
__device__ float g_bufB[NPAIR * 2 * EE];   // 4 MB pong
__device__ float g_pooledT[2 * EE * BB];   // [f][b]
__device__ float g_h1T[C1 * BB];           // [j][b]
__device__ float g_h2T[C2 * BB];           // [j][b]
__device__ int   g_meta[LL * NNODE + LL];  // per-(layer,node) counts, then per-layer item counts
__device__ int   g_list[LL * NNODE * LIST_CAP];
__device__ int   g_items[LL * ITEMS_MAX];  // packed (node<<6)|c0

// ---------------- f32x2 packed math ----------------
__device__ __forceinline__ void fma2(ull& d, ull a, ull b) {
    asm("fma.rn.f32x2 %0, %1, %2, %0;" : "+l"(d) : "l"(a), "l"(b));
}
__device__ __forceinline__ float hsum2(ull a) {
    return __uint_as_float((unsigned)a) + __uint_as_float((unsigned)(a >> 32));
}
__device__ __forceinline__ ull pack2(float x) {
    ull r; unsigned u = __float_as_uint(x);
    asm("mov.b64 %0, {%1, %2};" : "=l"(r) : "r"(u), "r"(u));
    return r;
}
__device__ __forceinline__ void cpasync16(uint32_t dst, const void* src) {
    asm volatile("cp.async.cg.shared.global [%0], [%1], 16;" :: "r"(dst), "l"(src));
}

// ---------------- list building: bucket pairs by (layer, node) ----------------
__global__ void build_lists_kernel(const int* __restrict__ mids)
{
    int idx = blockIdx.x * 256 + threadIdx.x;      // 0 .. NPAIR*LL-1
    if (idx >= NPAIR * LL) return;
    int p = idx >> 2, l = idx & 3;
    int node = mids[p * LL + l];
    int pos = atomicAdd(&g_meta[l * NNODE + node], 1);
    if (pos < LIST_CAP)
        g_list[(l * NNODE + node) * LIST_CAP + pos] = p;
}

// ---------------- item building: one item per (layer, node, 16-pair chunk) ----------------
__global__ void build_items_kernel()
{
    int idx = blockIdx.x * 256 + threadIdx.x;      // 0 .. LL*NNODE-1
    if (idx >= LL * NNODE) return;
    int l = idx >> 9, node = idx & (NNODE - 1);
    int c = g_meta[idx];
    c = c < LIST_CAP ? c : LIST_CAP;
    int nch = (c + 15) >> 4;
    if (nch > 0) {
        int base = atomicAdd(&g_meta[LL * NNODE + l], nch);
        for (int i = 0; i < nch; ++i)
            g_items[l * ITEMS_MAX + base + i] = (node << 6) | (i * 16);
    }
}

// ---------------- compute tile, M active vector-groups (compile-time) ----------------
// lane layout: rowlane = lane>>3 in [0,4), vl = lane&7 in [0,8)
// rows rl0 + {0,4,8,12} (16 rows per warp), vectors m*8+vl
template <int M>
__device__ __forceinline__ void compute_tile(
    const float* ws, const float* xs, const int* lst,
    float* bufOut, const float* bias_g,
    int w, int rowlane, int vl, int rh, int nv)
{
    const int rl0 = w * 16 + rowlane;      // local rows rl0 + {0,4,8,12}
    ull acc[M][4];
    #pragma unroll
    for (int m = 0; m < M; ++m)
        #pragma unroll
        for (int j = 0; j < 4; ++j) acc[m][j] = 0ull;

    #pragma unroll 4
    for (int is = 0; is < 32; ++is) {
        ulonglong2 wv[4];
        #pragma unroll
        for (int j = 0; j < 4; ++j)
            wv[j] = *(const ulonglong2*)&ws[(rl0 + 4 * j) * XSTR + is * 4];
        #pragma unroll
        for (int m = 0; m < M; ++m) {
            ulonglong2 xv = *(const ulonglong2*)&xs[(m * 8 + vl) * XSTR + is * 4];
            #pragma unroll
            for (int j = 0; j < 4; ++j) {
                fma2(acc[m][j], wv[j].x, xv.x);
                fma2(acc[m][j], wv[j].y, xv.y);
            }
        }
    }

    #pragma unroll
    for (int m = 0; m < M; ++m) {
        int v = m * 8 + vl;
        if (v < nv) {
            int pr = lst[v >> 1];
            float* dst = bufOut + ((size_t)pr * 2 + (v & 1)) * EE + rh * 64;
            #pragma unroll
            for (int j = 0; j < 4; ++j)
                dst[rl0 + 4 * j] = hsum2(acc[m][j]) + bias_g[rl0 + 4 * j];
        }
    }
}

// ---------------- persistent layer kernel with double-buffered prefetch ----------------
// dyn smem: 2 x (ws 64x132 + xs 32x132) floats = 101376 B -> 2 blocks/SM
#define SMEM_LAYER (2 * (64 * XSTR + 32 * XSTR) * 4)
#define WS_F (64 * XSTR)
#define XS_F (32 * XSTR)
#define BUF_F (WS_F + XS_F)

struct ItemSt { int node, c0, rh, nv; const int* lst; };

template <bool FIRST>
__device__ __forceinline__ ItemSt stage_item(
    float* sm, int buf, int work, int layer,
    const float* __restrict__ Wg,
    const int* __restrict__ sids, const int* __restrict__ eids,
    const float* __restrict__ embed, const float* __restrict__ bufIn,
    int tid, int lane, int w)
{
    ItemSt st;
    const int item = g_items[layer * ITEMS_MAX + (work >> 1)];
    st.node = item >> 6;
    st.c0   = item & 63;
    st.rh   = work & 1;
    int kp = g_meta[layer * NNODE + st.node];
    kp = kp < LIST_CAP ? kp : LIST_CAP;
    st.nv  = 2 * min(16, kp - st.c0);
    st.lst = &g_list[(layer * NNODE + st.node) * LIST_CAP + st.c0];

    float* ws = sm + buf * BUF_F;
    float* xs = ws + WS_F;
    uint32_t ws_u = (uint32_t)__cvta_generic_to_shared(ws);
    uint32_t xs_u = (uint32_t)__cvta_generic_to_shared(xs);

    // W rows for this row-half: warp w loads rows [w*16, +16)
    const float* wsrc = Wg + (size_t)st.node * (EE * EE) + (size_t)st.rh * 64 * EE;
    #pragma unroll
    for (int k = 0; k < 16; ++k) {
        int rl = w * 16 + k;
        cpasync16(ws_u + (rl * XSTR + lane * 4) * 4, wsrc + (size_t)rl * EE + lane * 4);
    }
    // xs: nv vectors x 32 float4 (no zero-fill; results beyond nv are discarded)
    for (int f = tid; f < st.nv * 32; f += 128) {
        int v = f >> 5, i4 = f & 31;
        int pr = st.lst[v >> 1];
        const float* src;
        if (FIRST) {
            int id = (v & 1) ? eids[pr] : sids[pr];
            src = embed + (size_t)id * EE;
        } else {
            src = bufIn + ((size_t)pr * 2 + (v & 1)) * EE;
        }
        cpasync16(xs_u + (v * XSTR + i4 * 4) * 4, src + i4 * 4);
    }
    asm volatile("cp.async.commit_group;");
    return st;
}

template <bool FIRST>
__global__ __launch_bounds__(128, 2) void layer_kernel(
    const float* __restrict__ Wg, const float* __restrict__ bias, int layer,
    const int* __restrict__ sids, const int* __restrict__ eids,
    const float* __restrict__ embed,
    const float* __restrict__ bufIn, float* __restrict__ bufOut)
{
    extern __shared__ float sm[];
    const int nwork = 2 * g_meta[LL * NNODE + layer];

    const int tid = threadIdx.x;
    const int lane = tid & 31, w = tid >> 5;
    const int rowlane = lane >> 3;       // 0..3  (matches compute_tile rows +{0,4,8,12})
    const int vl = lane & 7;             // 0..7  (matches xs index m*8+vl)

    int widx = blockIdx.x;
    if (widx >= nwork) return;

    int buf = 0;
    ItemSt cur = stage_item<FIRST>(sm, buf, widx, layer, Wg, sids, eids, embed, bufIn, tid, lane, w);
    int nxt_w = widx + PGRID;

    for (;;) {
        const bool has_next = (nxt_w < nwork);
        ItemSt nxt;
        if (has_next)
            nxt = stage_item<FIRST>(sm, buf ^ 1, nxt_w, layer, Wg, sids, eids, embed, bufIn, tid, lane, w);

        if (has_next) asm volatile("cp.async.wait_group 1;");
        else          asm volatile("cp.async.wait_group 0;");
        __syncthreads();                 // cur's data visible to all warps

        const float* ws = sm + buf * BUF_F;
        const float* xs = ws + WS_F;
        const float* bias_g = bias + cur.node * EE + cur.rh * 64;
        const int mmax = (cur.nv + 7) >> 3;
        switch (mmax) {
            case 1: compute_tile<1>(ws, xs, cur.lst, bufOut, bias_g, w, rowlane, vl, cur.rh, cur.nv); break;
            case 2: compute_tile<2>(ws, xs, cur.lst, bufOut, bias_g, w, rowlane, vl, cur.rh, cur.nv); break;
            case 3: compute_tile<3>(ws, xs, cur.lst, bufOut, bias_g, w, rowlane, vl, cur.rh, cur.nv); break;
            default: compute_tile<4>(ws, xs, cur.lst, bufOut, bias_g, w, rowlane, vl, cur.rh, cur.nv); break;
        }

        if (!has_next) break;
        __syncthreads();                 // all warps done with buf before restaging it
        cur = nxt;
        nxt_w += PGRID;
        buf ^= 1;
    }
}

// ---------------- pooling: pooledT[f][b] ----------------
__global__ void pool_kernel(const float* __restrict__ buf,
                            const int* __restrict__ counts,
                            float* __restrict__ pooledT)
{
    const int b = blockIdx.x;
    const int f = threadIdx.x;          // 0..255
    const int half = f >> 7, fi = f & 127;
    float acc = 0.f, cs = 0.f;
    #pragma unroll
    for (int p = 0; p < PP; ++p) {
        float c = (float)counts[b * PP + p];
        acc += c * buf[((size_t)((b * PP + p) * 2 + half)) * EE + fi];
        cs += c;
    }
    pooledT[(size_t)f * BB + b] = acc / cs;
}

// ---------------- MLP layer (relu): yT[j][b] ----------------
template <int IN>
__global__ void mlp_kernel(const float* __restrict__ Wm, const float* __restrict__ bm,
                           const float* __restrict__ xT, float* __restrict__ yT)
{
    __shared__ float wt[IN * 8];
    const int jt = blockIdx.x * 8;
    const int t = threadIdx.x;          // batch index
    for (int f = t; f < IN * 8; f += 256) {
        int jj = f / IN, i = f % IN;
        wt[i * 8 + jj] = Wm[(size_t)(jt + jj) * IN + i];
    }
    __syncthreads();

    ull acc[4] = {0ull, 0ull, 0ull, 0ull};
    #pragma unroll 8
    for (int i = 0; i < IN; ++i) {
        ull pp = pack2(xT[(size_t)i * BB + t]);
        ulonglong2 wa = *(ulonglong2*)&wt[i * 8];
        ulonglong2 wb = *(ulonglong2*)&wt[i * 8 + 4];
        fma2(acc[0], wa.x, pp);
        fma2(acc[1], wa.y, pp);
        fma2(acc[2], wb.x, pp);
        fma2(acc[3], wb.y, pp);
    }
    #pragma unroll
    for (int q = 0; q < 4; ++q) {
        int j0 = jt + 2 * q, j1 = j0 + 1;
        float v0 = __uint_as_float((unsigned)acc[q]) + bm[j0];
        float v1 = __uint_as_float((unsigned)(acc[q] >> 32)) + bm[j1];
        yT[(size_t)j0 * BB + t] = fmaxf(v0, 0.f);
        yT[(size_t)j1 * BB + t] = fmaxf(v1, 0.f);
    }
}

// ---------------- final ----------------
__global__ void out_kernel(const float* __restrict__ W3, const float* __restrict__ b3,
                           const float* __restrict__ h2T, float* __restrict__ out)
{
    const int t = threadIdx.x;
    float acc = 0.f;
    #pragma unroll 8
    for (int j = 0; j < C2; ++j)
        acc += W3[j] * h2T[(size_t)j * BB + t];
    acc += b3[0];
    out[t] = 1.f / (1.f + expf(-acc));
}

// ---------------- launch ----------------
extern "C" void kernel_launch(void* const* d_in, const int* in_sizes, int n_in,
                              void* d_out, int out_size)
{
    const int*   sids   = (const int*)d_in[0];
    const int*   eids   = (const int*)d_in[1];
    const int*   mids   = (const int*)d_in[2];
    const int*   counts = (const int*)d_in[3];
    const float* embed  = (const float*)d_in[4];
    const float* W      = (const float*)d_in[5];
    const float* bnode  = (const float*)d_in[6];
    const float* W1     = (const float*)d_in[7];
    const float* b1     = (const float*)d_in[8];
    const float* W2     = (const float*)d_in[9];
    const float* b2     = (const float*)d_in[10];
    const float* W3     = (const float*)d_in[11];
    const float* b3     = (const float*)d_in[12];

    float *bufA, *bufB, *pooledT, *h1T, *h2T;
    int *meta;
    cudaGetSymbolAddress((void**)&bufA, g_bufA);
    cudaGetSymbolAddress((void**)&bufB, g_bufB);
    cudaGetSymbolAddress((void**)&pooledT, g_pooledT);
    cudaGetSymbolAddress((void**)&h1T, g_h1T);
    cudaGetSymbolAddress((void**)&h2T, g_h2T);
    cudaGetSymbolAddress((void**)&meta, g_meta);

    const int smem = SMEM_LAYER;   // 101376 bytes
    cudaFuncSetAttribute(layer_kernel<true>,  cudaFuncAttributeMaxDynamicSharedMemorySize, smem);
    cudaFuncSetAttribute(layer_kernel<false>, cudaFuncAttributeMaxDynamicSharedMemorySize, smem);

    // reset counters + build node->pair lists + work items for all 4 layers
    cudaMemsetAsync(meta, 0, (LL * NNODE + LL) * sizeof(int));
    build_lists_kernel<<<(NPAIR * LL + 255) / 256, 256>>>(mids);
    build_items_kernel<<<(LL * NNODE + 255) / 256, 256>>>();

    layer_kernel<true ><<<PGRID, 128, smem>>>(W, bnode, 0, sids, eids, embed, nullptr, bufA);
    layer_kernel<false><<<PGRID, 128, smem>>>(W, bnode, 1, sids, eids, embed, bufA, bufB);
    layer_kernel<false><<<PGRID, 128, smem>>>(W, bnode, 2, sids, eids, embed, bufB, bufA);
    layer_kernel<false><<<PGRID, 128, smem>>>(W, bnode, 3, sids, eids, embed, bufA, bufB);

    pool_kernel<<<BB, 256>>>(bufB, counts, pooledT);
    mlp_kernel<2 * EE><<<C1 / 8, 256>>>(W1, b1, pooledT, h1T);
    mlp_kernel<C1>    <<<C2 / 8, 256>>>(W2, b2, h1T, h2T);
    out_kernel<<<1, 256>>>(W3, b3, h2T, (float*)d_out);
}

// round 12
// speedup vs baseline: 1.0243x; 1.0243x over previous
#include <cuda_runtime.h>
#include <cuda_bf16.h>
#include <cstdint>
#include <math.h>

// Problem constants (fixed by reference)
#define BB 256
#define PP 16
#define LL 4
#define EE 128
#define NPAIR 4096
#define NNODE 512
#define C1 512
#define C2 256
#define LIST_CAP 64
#define ITEMS_MAX 768        // >= 512 + 4096/16
#define XSTRH 136            // X row stride in bf16 units (272B) -> conflict-free B frags

typedef unsigned long long ull;
typedef unsigned short ushort_t;

// ---------------- device scratch (no allocations allowed) ----------------
__device__ float g_bufA[NPAIR * 2 * EE];   // 4 MB ping
__device__ float g_bufB[NPAIR * 2 * EE];   // 4 MB pong
__device__ float g_pooledT[2 * EE * BB];
__device__ float g_h1T[C1 * BB];
__device__ float g_h2T[C2 * BB];
__device__ int   g_meta[LL * NNODE + LL];
__device__ int   g_list[LL * NNODE * LIST_CAP];
__device__ int   g_items[LL * ITEMS_MAX];          // packed (node<<6)|c0
// W in bf16 hi/lo, FRAGMENT order: [node][mtile(8)][kstep(8)][lane(32)][reg(4)] u32
__device__ uint32_t g_Whi[NNODE * 8192];           // 16 MB
__device__ uint32_t g_Wlo[NNODE * 8192];           // 16 MB

// ---------------- helpers ----------------
__device__ __forceinline__ void fma2(ull& d, ull a, ull b) {
    asm("fma.rn.f32x2 %0, %1, %2, %0;" : "+l"(d) : "l"(a), "l"(b));
}
__device__ __forceinline__ ull pack2(float x) {
    ull r; unsigned u = __float_as_uint(x);
    asm("mov.b64 %0, {%1, %2};" : "=l"(r) : "r"(u), "r"(u));
    return r;
}
__device__ __forceinline__ void bf16split(float x, ushort_t& h, ushort_t& l) {
    __nv_bfloat16 hb = __float2bfloat16(x);
    float r = x - __bfloat162float(hb);
    __nv_bfloat16 lb = __float2bfloat16(r);
    h = __bfloat16_as_ushort(hb);
    l = __bfloat16_as_ushort(lb);
}
__device__ __forceinline__ void mma16816(float* c, const uint4& a, uint32_t b0, uint32_t b1) {
    asm volatile(
        "mma.sync.aligned.m16n8k16.row.col.f32.bf16.bf16.f32 "
        "{%0,%1,%2,%3}, {%4,%5,%6,%7}, {%8,%9}, {%0,%1,%2,%3};"
        : "+f"(c[0]), "+f"(c[1]), "+f"(c[2]), "+f"(c[3])
        : "r"(a.x), "r"(a.y), "r"(a.z), "r"(a.w), "r"(b0), "r"(b1));
}

// ---------------- list building ----------------
__global__ void build_lists_kernel(const int* __restrict__ mids)
{
    int idx = blockIdx.x * 256 + threadIdx.x;
    if (idx >= NPAIR * LL) return;
    int p = idx >> 2, l = idx & 3;
    int node = mids[p * LL + l];
    int pos = atomicAdd(&g_meta[l * NNODE + node], 1);
    if (pos < LIST_CAP)
        g_list[(l * NNODE + node) * LIST_CAP + pos] = p;
}

// ---------------- item building: (layer, node, 16-pair chunk) ----------------
__global__ void build_items_kernel()
{
    int idx = blockIdx.x * 256 + threadIdx.x;
    if (idx >= LL * NNODE) return;
    int l = idx >> 9, node = idx & (NNODE - 1);
    int c = g_meta[idx];
    c = c < LIST_CAP ? c : LIST_CAP;
    int nch = (c + 15) >> 4;
    if (nch > 0) {
        int base = atomicAdd(&g_meta[LL * NNODE + l], nch);
        for (int i = 0; i < nch; ++i)
            g_items[l * ITEMS_MAX + base + i] = (node << 6) | (i * 16);
    }
}

// ---------------- W -> bf16 hi/lo in mma fragment order ----------------
// For fragment index i = ((m*8+s)*32 + lane)*4 + q:
//   r = m*16 + (lane>>2) + ((q&1)<<3)
//   k = s*16 + ((lane&3)<<1) + ((q>>1)<<3)
//   value = pack(W[r][k], W[r][k+1])
__global__ void convert_w_kernel(const float* __restrict__ W)
{
    int node = blockIdx.x;
    const float* src = W + (size_t)node * EE * EE;
    uint32_t* dh = g_Whi + node * 8192;
    uint32_t* dl = g_Wlo + node * 8192;
    for (int i = threadIdx.x; i < 8192; i += 256) {
        int q = i & 3, l = (i >> 2) & 31, s = (i >> 7) & 7, m = i >> 10;
        int r = m * 16 + (l >> 2) + ((q & 1) << 3);
        int k = s * 16 + ((l & 3) << 1) + ((q >> 1) << 3);
        float x0 = src[r * EE + k], x1 = src[r * EE + k + 1];
        ushort_t h0, l0, h1, l1;
        bf16split(x0, h0, l0);
        bf16split(x1, h1, l1);
        dh[i] = (uint32_t)h0 | ((uint32_t)h1 << 16);
        dl[i] = (uint32_t)l0 | ((uint32_t)l1 << 16);
    }
}

// ---------------- layer kernel: one block per (node, 16-pair chunk) item ----------------
// 128 threads = 4 warps; warp w computes rows [w*32, w*32+32) x all 32 vectors.
// A fragments streamed from global (fragment-ordered), X hi/lo tiles in smem.
template <bool FIRST>
__global__ __launch_bounds__(128) void layer_mma_kernel(
    int layer, const float* __restrict__ bias,
    const int* __restrict__ sids, const int* __restrict__ eids,
    const float* __restrict__ embed,
    const float* __restrict__ bufIn, float* __restrict__ bufOut)
{
    const int nitems = g_meta[LL * NNODE + layer];
    if ((int)blockIdx.x >= nitems) return;

    __shared__ ushort_t sxh[32 * XSTRH];
    __shared__ ushort_t sxl[32 * XSTRH];

    const int item = g_items[layer * ITEMS_MAX + blockIdx.x];
    const int node = item >> 6;
    const int c0   = item & 63;
    int kp = g_meta[layer * NNODE + node];
    kp = kp < LIST_CAP ? kp : LIST_CAP;
    const int nv = 2 * min(16, kp - c0);
    const int* lst = &g_list[(layer * NNODE + node) * LIST_CAP + c0];

    const int tid = threadIdx.x, lane = tid & 31, w = tid >> 5;

    // ---- gather X, split into bf16 hi/lo tiles (vectors >= nv left stale; discarded) ----
    for (int f = tid; f < nv * 32; f += 128) {
        int v = f >> 5, i4 = f & 31;
        int pr = lst[v >> 1];
        const float4* src;
        if (FIRST) {
            int id = (v & 1) ? eids[pr] : sids[pr];
            src = (const float4*)(embed + (size_t)id * EE);
        } else {
            src = (const float4*)(bufIn + ((size_t)pr * 2 + (v & 1)) * EE);
        }
        float4 x = src[i4];
        ushort_t h0,l0,h1,l1,h2,l2,h3,l3;
        bf16split(x.x, h0, l0); bf16split(x.y, h1, l1);
        bf16split(x.z, h2, l2); bf16split(x.w, h3, l3);
        int o = v * XSTRH + i4 * 4;
        *(uint2*)&sxh[o] = make_uint2((uint32_t)h0 | ((uint32_t)h1 << 16),
                                      (uint32_t)h2 | ((uint32_t)h3 << 16));
        *(uint2*)&sxl[o] = make_uint2((uint32_t)l0 | ((uint32_t)l1 << 16),
                                      (uint32_t)l2 | ((uint32_t)l3 << 16));
    }
    __syncthreads();

    // ---- 3-product bf16-split mma: Whi*Xhi + Whi*Xlo + Wlo*Xhi ----
    float c[2][4][4];
    #pragma unroll
    for (int mt = 0; mt < 2; ++mt)
        #pragma unroll
        for (int nt = 0; nt < 4; ++nt)
            #pragma unroll
            for (int q = 0; q < 4; ++q) c[mt][nt][q] = 0.f;

    const uint4* whiF = (const uint4*)(g_Whi + node * 8192);
    const uint4* wloF = (const uint4*)(g_Wlo + node * 8192);
    const int m0 = 2 * w, m1 = 2 * w + 1;      // this warp's mtiles
    const int brow = lane >> 2;                // B frag: n offset within ntile
    const int bcol = (lane & 3) << 1;          // B frag: k pair base

    #pragma unroll 1
    for (int p = 0; p < 3; ++p) {
        const uint4* wf = (p < 2) ? whiF : wloF;
        const ushort_t* xb = (p == 1) ? sxl : sxh;
        #pragma unroll
        for (int s = 0; s < 8; ++s) {
            uint4 A0 = wf[(m0 * 8 + s) * 32 + lane];
            uint4 A1 = wf[(m1 * 8 + s) * 32 + lane];
            #pragma unroll
            for (int nt = 0; nt < 4; ++nt) {
                const ushort_t* xr = xb + (nt * 8 + brow) * XSTRH + s * 16 + bcol;
                uint32_t b0 = *(const uint32_t*)xr;
                uint32_t b1 = *(const uint32_t*)(xr + 8);
                mma16816(c[0][nt], A0, b0, b1);
                mma16816(c[1][nt], A1, b0, b1);
            }
        }
    }

    // ---- epilogue: +bias, guarded scatter ----
    #pragma unroll
    for (int mt = 0; mt < 2; ++mt) {
        const int r0 = w * 32 + mt * 16 + (lane >> 2);
        const float bv0 = bias[node * EE + r0];
        const float bv1 = bias[node * EE + r0 + 8];
        #pragma unroll
        for (int nt = 0; nt < 4; ++nt) {
            int v0 = nt * 8 + ((lane & 3) << 1);
            int v1 = v0 + 1;
            if (v0 < nv) {
                int pr = lst[v0 >> 1];
                float* dst = bufOut + ((size_t)pr * 2 + (v0 & 1)) * EE;
                dst[r0]     = c[mt][nt][0] + bv0;
                dst[r0 + 8] = c[mt][nt][2] + bv1;
            }
            if (v1 < nv) {
                int pr = lst[v1 >> 1];
                float* dst = bufOut + ((size_t)pr * 2 + (v1 & 1)) * EE;
                dst[r0]     = c[mt][nt][1] + bv0;
                dst[r0 + 8] = c[mt][nt][3] + bv1;
            }
        }
    }
}

// ---------------- pooling: pooledT[f][b] ----------------
__global__ void pool_kernel(const float* __restrict__ buf,
                            const int* __restrict__ counts,
                            float* __restrict__ pooledT)
{
    const int b = blockIdx.x;
    const int f = threadIdx.x;
    const int half = f >> 7, fi = f & 127;
    float acc = 0.f, cs = 0.f;
    #pragma unroll
    for (int p = 0; p < PP; ++p) {
        float c = (float)counts[b * PP + p];
        acc += c * buf[((size_t)((b * PP + p) * 2 + half)) * EE + fi];
        cs += c;
    }
    pooledT[(size_t)f * BB + b] = acc / cs;
}

// ---------------- MLP layer (relu): yT[j][b] ----------------
template <int IN>
__global__ void mlp_kernel(const float* __restrict__ Wm, const float* __restrict__ bm,
                           const float* __restrict__ xT, float* __restrict__ yT)
{
    __shared__ float wt[IN * 8];
    const int jt = blockIdx.x * 8;
    const int t = threadIdx.x;
    for (int f = t; f < IN * 8; f += 256) {
        int jj = f / IN, i = f % IN;
        wt[i * 8 + jj] = Wm[(size_t)(jt + jj) * IN + i];
    }
    __syncthreads();

    ull acc[4] = {0ull, 0ull, 0ull, 0ull};
    #pragma unroll 8
    for (int i = 0; i < IN; ++i) {
        ull pp = pack2(xT[(size_t)i * BB + t]);
        ulonglong2 wa = *(ulonglong2*)&wt[i * 8];
        ulonglong2 wb = *(ulonglong2*)&wt[i * 8 + 4];
        fma2(acc[0], wa.x, pp);
        fma2(acc[1], wa.y, pp);
        fma2(acc[2], wb.x, pp);
        fma2(acc[3], wb.y, pp);
    }
    #pragma unroll
    for (int q = 0; q < 4; ++q) {
        int j0 = jt + 2 * q, j1 = j0 + 1;
        float v0 = __uint_as_float((unsigned)acc[q]) + bm[j0];
        float v1 = __uint_as_float((unsigned)(acc[q] >> 32)) + bm[j1];
        yT[(size_t)j0 * BB + t] = fmaxf(v0, 0.f);
        yT[(size_t)j1 * BB + t] = fmaxf(v1, 0.f);
    }
}

// ---------------- final ----------------
__global__ void out_kernel(const float* __restrict__ W3, const float* __restrict__ b3,
                           const float* __restrict__ h2T, float* __restrict__ out)
{
    const int t = threadIdx.x;
    float acc = 0.f;
    #pragma unroll 8
    for (int j = 0; j < C2; ++j)
        acc += W3[j] * h2T[(size_t)j * BB + t];
    acc += b3[0];
    out[t] = 1.f / (1.f + expf(-acc));
}

// ---------------- launch ----------------
extern "C" void kernel_launch(void* const* d_in, const int* in_sizes, int n_in,
                              void* d_out, int out_size)
{
    const int*   sids   = (const int*)d_in[0];
    const int*   eids   = (const int*)d_in[1];
    const int*   mids   = (const int*)d_in[2];
    const int*   counts = (const int*)d_in[3];
    const float* embed  = (const float*)d_in[4];
    const float* W      = (const float*)d_in[5];
    const float* bnode  = (const float*)d_in[6];
    const float* W1     = (const float*)d_in[7];
    const float* b1     = (const float*)d_in[8];
    const float* W2     = (const float*)d_in[9];
    const float* b2     = (const float*)d_in[10];
    const float* W3     = (const float*)d_in[11];
    const float* b3     = (const float*)d_in[12];

    float *bufA, *bufB, *pooledT, *h1T, *h2T;
    int *meta;
    cudaGetSymbolAddress((void**)&bufA, g_bufA);
    cudaGetSymbolAddress((void**)&bufB, g_bufB);
    cudaGetSymbolAddress((void**)&pooledT, g_pooledT);
    cudaGetSymbolAddress((void**)&h1T, g_h1T);
    cudaGetSymbolAddress((void**)&h2T, g_h2T);
    cudaGetSymbolAddress((void**)&meta, g_meta);

    // metadata + fragment-ordered bf16 hi/lo weights
    cudaMemsetAsync(meta, 0, (LL * NNODE + LL) * sizeof(int));
    build_lists_kernel<<<(NPAIR * LL + 255) / 256, 256>>>(mids);
    build_items_kernel<<<(LL * NNODE + 255) / 256, 256>>>();
    convert_w_kernel<<<NNODE, 256>>>(W);

    layer_mma_kernel<true ><<<ITEMS_MAX, 128>>>(0, bnode, sids, eids, embed, nullptr, bufA);
    layer_mma_kernel<false><<<ITEMS_MAX, 128>>>(1, bnode, sids, eids, embed, bufA, bufB);
    layer_mma_kernel<false><<<ITEMS_MAX, 128>>>(2, bnode, sids, eids, embed, bufB, bufA);
    layer_mma_kernel<false><<<ITEMS_MAX, 128>>>(3, bnode, sids, eids, embed, bufA, bufB);

    pool_kernel<<<BB, 256>>>(bufB, counts, pooledT);
    mlp_kernel<2 * EE><<<C1 / 8, 256>>>(W1, b1, pooledT, h1T);
    mlp_kernel<C1>    <<<C2 / 8, 256>>>(W2, b2, h1T, h2T);
    out_kernel<<<1, 256>>>(W3, b3, h2T, (float*)d_out);
}

// round 13
// speedup vs baseline: 1.2407x; 1.2112x over previous
#include <cuda_runtime.h>
#include <cuda_bf16.h>
#include <cstdint>
#include <math.h>

// Problem constants (fixed by reference)
#define BB 256
#define PP 16
#define LL 4
#define EE 128
#define NPAIR 4096
#define NNODE 512
#define C1 512
#define C2 256
#define LIST_CAP 64
#define ITEMS_MAX 768        // >= 512 + 4096/16
#define XSTRH 136            // X row stride in bf16 units (272B) -> conflict-free B frags

typedef unsigned long long ull;
typedef unsigned short ushort_t;

// ---------------- device scratch (no allocations allowed) ----------------
__device__ float g_bufA[NPAIR * 2 * EE];   // 4 MB ping
__device__ float g_bufB[NPAIR * 2 * EE];   // 4 MB pong
__device__ float g_pooledT[2 * EE * BB];
__device__ float g_h1T[C1 * BB];
__device__ float g_h2T[C2 * BB];
__device__ int   g_meta[LL * NNODE + LL];
__device__ int   g_list[LL * NNODE * LIST_CAP];
__device__ int   g_items[LL * ITEMS_MAX];          // packed (node<<6)|c0

// ---------------- helpers ----------------
__device__ __forceinline__ void fma2(ull& d, ull a, ull b) {
    asm("fma.rn.f32x2 %0, %1, %2, %0;" : "+l"(d) : "l"(a), "l"(b));
}
__device__ __forceinline__ ull pack2(float x) {
    ull r; unsigned u = __float_as_uint(x);
    asm("mov.b64 %0, {%1, %2};" : "=l"(r) : "r"(u), "r"(u));
    return r;
}
// pack two floats into bf16x2 (x0 -> low half, x1 -> high half)
__device__ __forceinline__ uint32_t cvt_bf16x2(float x0, float x1) {
    uint32_t r;
    asm("cvt.rn.bf16x2.f32 %0, %1, %2;" : "=r"(r) : "f"(x1), "f"(x0));
    return r;
}
// given float2 (x0,x1): produce hi-pack and lo-pack (residual) bf16x2
__device__ __forceinline__ void split2(float x0, float x1, uint32_t& hi, uint32_t& lo) {
    hi = cvt_bf16x2(x0, x1);
    float h0 = __uint_as_float(hi << 16);
    float h1 = __uint_as_float(hi & 0xffff0000u);
    lo = cvt_bf16x2(x0 - h0, x1 - h1);
}
__device__ __forceinline__ void mma16816(float* c, uint32_t a0, uint32_t a1, uint32_t a2, uint32_t a3,
                                         uint32_t b0, uint32_t b1) {
    asm volatile(
        "mma.sync.aligned.m16n8k16.row.col.f32.bf16.bf16.f32 "
        "{%0,%1,%2,%3}, {%4,%5,%6,%7}, {%8,%9}, {%0,%1,%2,%3};"
        : "+f"(c[0]), "+f"(c[1]), "+f"(c[2]), "+f"(c[3])
        : "r"(a0), "r"(a1), "r"(a2), "r"(a3), "r"(b0), "r"(b1));
}

// ---------------- list building ----------------
__global__ void build_lists_kernel(const int* __restrict__ mids)
{
    int idx = blockIdx.x * 256 + threadIdx.x;
    if (idx >= NPAIR * LL) return;
    int p = idx >> 2, l = idx & 3;
    int node = mids[p * LL + l];
    int pos = atomicAdd(&g_meta[l * NNODE + node], 1);
    if (pos < LIST_CAP)
        g_list[(l * NNODE + node) * LIST_CAP + pos] = p;
}

// ---------------- item building: (layer, node, 16-pair chunk) ----------------
__global__ void build_items_kernel()
{
    int idx = blockIdx.x * 256 + threadIdx.x;
    if (idx >= LL * NNODE) return;
    int l = idx >> 9, node = idx & (NNODE - 1);
    int c = g_meta[idx];
    c = c < LIST_CAP ? c : LIST_CAP;
    int nch = (c + 15) >> 4;
    if (nch > 0) {
        int base = atomicAdd(&g_meta[LL * NNODE + l], nch);
        for (int i = 0; i < nch; ++i)
            g_items[l * ITEMS_MAX + base + i] = (node << 6) | (i * 16);
    }
}

// ---------------- layer kernel: one block per (node, 16-pair chunk) item ----------------
// 128 threads = 4 warps; warp w computes rows [w*32, w*32+32) x 32 vectors.
// W loaded fp32 straight from the input tensor (fragment pattern), split to bf16
// hi/lo in registers; each W element read ONCE and reused by all 3 split-products.
template <bool FIRST>
__global__ __launch_bounds__(128) void layer_mma_kernel(
    int layer, const float* __restrict__ Wg, const float* __restrict__ bias,
    const int* __restrict__ sids, const int* __restrict__ eids,
    const float* __restrict__ embed,
    const float* __restrict__ bufIn, float* __restrict__ bufOut)
{
    const int nitems = g_meta[LL * NNODE + layer];
    if ((int)blockIdx.x >= nitems) return;

    __shared__ ushort_t sxh[32 * XSTRH];
    __shared__ ushort_t sxl[32 * XSTRH];

    const int item = g_items[layer * ITEMS_MAX + blockIdx.x];
    const int node = item >> 6;
    const int c0   = item & 63;
    int kp = g_meta[layer * NNODE + node];
    kp = kp < LIST_CAP ? kp : LIST_CAP;
    const int nv = 2 * min(16, kp - c0);
    const int* lst = &g_list[(layer * NNODE + node) * LIST_CAP + c0];

    const int tid = threadIdx.x, lane = tid & 31, w = tid >> 5;

    // ---- gather X, split into bf16 hi/lo tiles (vectors >= nv stale; discarded) ----
    for (int f = tid; f < nv * 32; f += 128) {
        int v = f >> 5, i4 = f & 31;
        int pr = lst[v >> 1];
        const float4* src;
        if (FIRST) {
            int id = (v & 1) ? eids[pr] : sids[pr];
            src = (const float4*)(embed + (size_t)id * EE);
        } else {
            src = (const float4*)(bufIn + ((size_t)pr * 2 + (v & 1)) * EE);
        }
        float4 x = src[i4];
        uint32_t h01, l01, h23, l23;
        split2(x.x, x.y, h01, l01);
        split2(x.z, x.w, h23, l23);
        int o = v * XSTRH + i4 * 4;
        *(uint2*)&sxh[o] = make_uint2(h01, h23);
        *(uint2*)&sxl[o] = make_uint2(l01, l23);
    }
    __syncthreads();

    // ---- 3-product bf16-split mma: Whi*Xhi + Whi*Xlo + Wlo*Xhi ----
    float c[2][4][4];
    #pragma unroll
    for (int mt = 0; mt < 2; ++mt)
        #pragma unroll
        for (int nt = 0; nt < 4; ++nt)
            #pragma unroll
            for (int q = 0; q < 4; ++q) c[mt][nt][q] = 0.f;

    const float* Wn = Wg + (size_t)node * EE * EE;
    const int rbase = w * 32 + (lane >> 2);    // A frag row (mt adds 16, q adds 8)
    const int kbase = (lane & 3) << 1;         // A/B frag k pair base
    const int brow = lane >> 2;                // B frag: n offset within ntile

    #pragma unroll 2
    for (int s = 0; s < 8; ++s) {
        const int ks = s * 16 + kbase;
        // load this warp's W fp32 fragment elements (each element exactly once)
        uint32_t ahi[2][4], alo[2][4];
        #pragma unroll
        for (int mt = 0; mt < 2; ++mt) {
            const float* wr0 = Wn + (size_t)(rbase + mt * 16) * EE + ks;
            const float* wr1 = wr0 + 8 * EE;
            float2 w00 = *(const float2*)wr0;          // (r,   k..k+1)
            float2 w10 = *(const float2*)wr1;          // (r+8, k..k+1)
            float2 w01 = *(const float2*)(wr0 + 8);    // (r,   k+8..k+9)
            float2 w11 = *(const float2*)(wr1 + 8);    // (r+8, k+8..k+9)
            split2(w00.x, w00.y, ahi[mt][0], alo[mt][0]);
            split2(w10.x, w10.y, ahi[mt][1], alo[mt][1]);
            split2(w01.x, w01.y, ahi[mt][2], alo[mt][2]);
            split2(w11.x, w11.y, ahi[mt][3], alo[mt][3]);
        }
        #pragma unroll
        for (int nt = 0; nt < 4; ++nt) {
            const int xo = (nt * 8 + brow) * XSTRH + s * 16 + kbase;
            uint32_t bh0 = *(const uint32_t*)&sxh[xo];
            uint32_t bh1 = *(const uint32_t*)&sxh[xo + 8];
            uint32_t bl0 = *(const uint32_t*)&sxl[xo];
            uint32_t bl1 = *(const uint32_t*)&sxl[xo + 8];
            #pragma unroll
            for (int mt = 0; mt < 2; ++mt) {
                mma16816(c[mt][nt], ahi[mt][0], ahi[mt][1], ahi[mt][2], ahi[mt][3], bh0, bh1);
                mma16816(c[mt][nt], ahi[mt][0], ahi[mt][1], ahi[mt][2], ahi[mt][3], bl0, bl1);
                mma16816(c[mt][nt], alo[mt][0], alo[mt][1], alo[mt][2], alo[mt][3], bh0, bh1);
            }
        }
    }

    // ---- epilogue: +bias, guarded scatter ----
    #pragma unroll
    for (int mt = 0; mt < 2; ++mt) {
        const int r0 = w * 32 + mt * 16 + (lane >> 2);
        const float bv0 = bias[node * EE + r0];
        const float bv1 = bias[node * EE + r0 + 8];
        #pragma unroll
        for (int nt = 0; nt < 4; ++nt) {
            int v0 = nt * 8 + ((lane & 3) << 1);
            int v1 = v0 + 1;
            if (v0 < nv) {
                int pr = lst[v0 >> 1];
                float* dst = bufOut + ((size_t)pr * 2 + (v0 & 1)) * EE;
                dst[r0]     = c[mt][nt][0] + bv0;
                dst[r0 + 8] = c[mt][nt][2] + bv1;
            }
            if (v1 < nv) {
                int pr = lst[v1 >> 1];
                float* dst = bufOut + ((size_t)pr * 2 + (v1 & 1)) * EE;
                dst[r0]     = c[mt][nt][1] + bv0;
                dst[r0 + 8] = c[mt][nt][3] + bv1;
            }
        }
    }
}

// ---------------- pooling: pooledT[f][b] ----------------
__global__ void pool_kernel(const float* __restrict__ buf,
                            const int* __restrict__ counts,
                            float* __restrict__ pooledT)
{
    const int b = blockIdx.x;
    const int f = threadIdx.x;
    const int half = f >> 7, fi = f & 127;
    float acc = 0.f, cs = 0.f;
    #pragma unroll
    for (int p = 0; p < PP; ++p) {
        float c = (float)counts[b * PP + p];
        acc += c * buf[((size_t)((b * PP + p) * 2 + half)) * EE + fi];
        cs += c;
    }
    pooledT[(size_t)f * BB + b] = acc / cs;
}

// ---------------- MLP layer (relu): yT[j][b] ----------------
template <int IN>
__global__ void mlp_kernel(const float* __restrict__ Wm, const float* __restrict__ bm,
                           const float* __restrict__ xT, float* __restrict__ yT)
{
    __shared__ float wt[IN * 8];
    const int jt = blockIdx.x * 8;
    const int t = threadIdx.x;
    for (int f = t; f < IN * 8; f += 256) {
        int jj = f / IN, i = f % IN;
        wt[i * 8 + jj] = Wm[(size_t)(jt + jj) * IN + i];
    }
    __syncthreads();

    ull acc[4] = {0ull, 0ull, 0ull, 0ull};
    #pragma unroll 8
    for (int i = 0; i < IN; ++i) {
        ull pp = pack2(xT[(size_t)i * BB + t]);
        ulonglong2 wa = *(ulonglong2*)&wt[i * 8];
        ulonglong2 wb = *(ulonglong2*)&wt[i * 8 + 4];
        fma2(acc[0], wa.x, pp);
        fma2(acc[1], wa.y, pp);
        fma2(acc[2], wb.x, pp);
        fma2(acc[3], wb.y, pp);
    }
    #pragma unroll
    for (int q = 0; q < 4; ++q) {
        int j0 = jt + 2 * q, j1 = j0 + 1;
        float v0 = __uint_as_float((unsigned)acc[q]) + bm[j0];
        float v1 = __uint_as_float((unsigned)(acc[q] >> 32)) + bm[j1];
        yT[(size_t)j0 * BB + t] = fmaxf(v0, 0.f);
        yT[(size_t)j1 * BB + t] = fmaxf(v1, 0.f);
    }
}

// ---------------- final ----------------
__global__ void out_kernel(const float* __restrict__ W3, const float* __restrict__ b3,
                           const float* __restrict__ h2T, float* __restrict__ out)
{
    const int t = threadIdx.x;
    float acc = 0.f;
    #pragma unroll 8
    for (int j = 0; j < C2; ++j)
        acc += W3[j] * h2T[(size_t)j * BB + t];
    acc += b3[0];
    out[t] = 1.f / (1.f + expf(-acc));
}

// ---------------- launch ----------------
extern "C" void kernel_launch(void* const* d_in, const int* in_sizes, int n_in,
                              void* d_out, int out_size)
{
    const int*   sids   = (const int*)d_in[0];
    const int*   eids   = (const int*)d_in[1];
    const int*   mids   = (const int*)d_in[2];
    const int*   counts = (const int*)d_in[3];
    const float* embed  = (const float*)d_in[4];
    const float* W      = (const float*)d_in[5];
    const float* bnode  = (const float*)d_in[6];
    const float* W1     = (const float*)d_in[7];
    const float* b1     = (const float*)d_in[8];
    const float* W2     = (const float*)d_in[9];
    const float* b2     = (const float*)d_in[10];
    const float* W3     = (const float*)d_in[11];
    const float* b3     = (const float*)d_in[12];

    float *bufA, *bufB, *pooledT, *h1T, *h2T;
    int *meta;
    cudaGetSymbolAddress((void**)&bufA, g_bufA);
    cudaGetSymbolAddress((void**)&bufB, g_bufB);
    cudaGetSymbolAddress((void**)&pooledT, g_pooledT);
    cudaGetSymbolAddress((void**)&h1T, g_h1T);
    cudaGetSymbolAddress((void**)&h2T, g_h2T);
    cudaGetSymbolAddress((void**)&meta, g_meta);

    // metadata
    cudaMemsetAsync(meta, 0, (LL * NNODE + LL) * sizeof(int));
    build_lists_kernel<<<(NPAIR * LL + 255) / 256, 256>>>(mids);
    build_items_kernel<<<(LL * NNODE + 255) / 256, 256>>>();

    layer_mma_kernel<true ><<<ITEMS_MAX, 128>>>(0, W, bnode, sids, eids, embed, nullptr, bufA);
    layer_mma_kernel<false><<<ITEMS_MAX, 128>>>(1, W, bnode, sids, eids, embed, bufA, bufB);
    layer_mma_kernel<false><<<ITEMS_MAX, 128>>>(2, W, bnode, sids, eids, embed, bufB, bufA);
    layer_mma_kernel<false><<<ITEMS_MAX, 128>>>(3, W, bnode, sids, eids, embed, bufA, bufB);

    pool_kernel<<<BB, 256>>>(bufB, counts, pooledT);
    mlp_kernel<2 * EE><<<C1 / 8, 256>>>(W1, b1, pooledT, h1T);
    mlp_kernel<C1>    <<<C2 / 8, 256>>>(W2, b2, h1T, h2T);
    out_kernel<<<1, 256>>>(W3, b3, h2T, (float*)d_out);
}